// round 2
// baseline (speedup 1.0000x reference)
#include <cuda_runtime.h>
#include <math.h>

// Problem constants
#define TLEN   2048
#define NHEAD  16
#define HDIM   64
#define NFEAT  128
#define BATCH  4
#define BH     64          // BATCH*NHEAD
#define NROWS  8192        // BATCH*TLEN
#define DM     1024
#define NCH    32          // chunks per sequence
#define CHK    64          // chunk length
#define EPS_F  1e-6f
#define INV_SQRT_NF 0.08838834764831843f

// -------------------- scratch (device globals; no allocations allowed) -----
__device__ float g_q [NROWS * DM];
__device__ float g_k [NROWS * DM];
__device__ float g_v [NROWS * DM];
__device__ float g_y [NROWS * DM];
__device__ float g_qp[(size_t)BH * TLEN * NFEAT];
__device__ float g_kp[(size_t)BH * TLEN * NFEAT];
__device__ float g_kv[(size_t)BH * NCH * NFEAT * HDIM];   // per-chunk K^T V, then exclusive prefix
__device__ float g_zc[(size_t)BH * NCH * NFEAT];          // per-chunk k-sum, then exclusive prefix

// ===========================================================================
// SGEMM: C[M,N] = A[M,K] @ B[K,N], all row-major, M%128==0, N%128==0, K%16==0
// 128x128 tile, BK=16, 256 threads, 8x8 per-thread register tile.
// ===========================================================================
__global__ __launch_bounds__(256, 2)
void sgemm128(const float* __restrict__ A, const float* __restrict__ B,
              float* __restrict__ C, int M, int N, int K)
{
    __shared__ float As[16][132];   // transposed: As[k][m]
    __shared__ float Bs[16][132];   // Bs[k][n]

    const int tid = threadIdx.x;
    const int bm  = blockIdx.y * 128;
    const int bn  = blockIdx.x * 128;
    const int tr  = tid >> 4;       // 0..15
    const int tc  = tid & 15;       // 0..15

    float acc[8][8];
#pragma unroll
    for (int i = 0; i < 8; i++)
#pragma unroll
        for (int j = 0; j < 8; j++) acc[i][j] = 0.f;

    for (int k0 = 0; k0 < K; k0 += 16) {
#pragma unroll
        for (int it = 0; it < 2; it++) {
            int v = tid + it * 256;
            // A tile: 128 rows x 16 cols
            int r  = v >> 2;
            int kg = (v & 3) * 4;
            float4 a = *(const float4*)&A[(size_t)(bm + r) * K + k0 + kg];
            As[kg + 0][r] = a.x;
            As[kg + 1][r] = a.y;
            As[kg + 2][r] = a.z;
            As[kg + 3][r] = a.w;
            // B tile: 16 rows x 128 cols
            int rb = v >> 5;
            int cb = (v & 31) * 4;
            float4 b = *(const float4*)&B[(size_t)(k0 + rb) * N + bn + cb];
            *(float4*)&Bs[rb][cb] = b;
        }
        __syncthreads();

#pragma unroll
        for (int kk = 0; kk < 16; kk++) {
            float a[8], b[8];
            *(float4*)&a[0] = *(float4*)&As[kk][tr * 8];
            *(float4*)&a[4] = *(float4*)&As[kk][tr * 8 + 4];
            *(float4*)&b[0] = *(float4*)&Bs[kk][tc * 8];
            *(float4*)&b[4] = *(float4*)&Bs[kk][tc * 8 + 4];
#pragma unroll
            for (int i = 0; i < 8; i++)
#pragma unroll
                for (int j = 0; j < 8; j++)
                    acc[i][j] += a[i] * b[j];
        }
        __syncthreads();
    }

#pragma unroll
    for (int i = 0; i < 8; i++) {
        size_t row = (size_t)(bm + tr * 8 + i) * N + bn + tc * 8;
        *(float4*)&C[row]     = make_float4(acc[i][0], acc[i][1], acc[i][2], acc[i][3]);
        *(float4*)&C[row + 4] = make_float4(acc[i][4], acc[i][5], acc[i][6], acc[i][7]);
    }
}

// ===========================================================================
// Feature map: dst[bh][t][f] = exp( q . Wf[:,f] - 0.5*|q|^2 ) * INV_SQRT_NF
// One block per (bh, 64-row chunk). src layout: [b*T + t][h*64 + d].
// ===========================================================================
__global__ __launch_bounds__(256)
void feat_kernel(const float* __restrict__ src, const float* __restrict__ Wf,
                 float* __restrict__ dst)
{
    extern __shared__ float sm[];
    float* Wfs = sm;                  // 64*128 = 8192
    float* qs  = sm + 8192;           // 64*64  = 4096
    float* sqs = sm + 8192 + 4096;    // 64

    const int bh = blockIdx.x >> 5;
    const int c  = blockIdx.x & 31;
    const int b  = bh >> 4, h = bh & 15;
    const int t0 = c * CHK;
    const int tid = threadIdx.x;

    for (int i = tid; i < 8192; i += 256) Wfs[i] = Wf[i];           // [d*128+f]
    for (int i = tid; i < 4096; i += 256) {
        int t = i >> 6, d = i & 63;
        qs[i] = src[(size_t)(b * TLEN + t0 + t) * DM + h * HDIM + d];
    }
    __syncthreads();

    if (tid < 64) {
        float s = 0.f;
#pragma unroll 16
        for (int d = 0; d < 64; d++) { float x = qs[tid * 64 + d]; s += x * x; }
        sqs[tid] = 0.5f * s;
    }
    __syncthreads();

    const int tg = tid >> 4;   // 0..15 -> 4 t rows
    const int fg = tid & 15;   // 0..15 -> 8 f cols
    float acc[4][8];
#pragma unroll
    for (int i = 0; i < 4; i++)
#pragma unroll
        for (int j = 0; j < 8; j++) acc[i][j] = 0.f;

#pragma unroll 8
    for (int d = 0; d < 64; d++) {
        float w[8];
        *(float4*)&w[0] = *(float4*)&Wfs[d * 128 + fg * 8];
        *(float4*)&w[4] = *(float4*)&Wfs[d * 128 + fg * 8 + 4];
#pragma unroll
        for (int i = 0; i < 4; i++) {
            float qv = qs[(tg * 4 + i) * 64 + d];
#pragma unroll
            for (int j = 0; j < 8; j++) acc[i][j] += qv * w[j];
        }
    }

#pragma unroll
    for (int i = 0; i < 4; i++) {
        int t = tg * 4 + i;
        float sq = sqs[t];
        float o[8];
#pragma unroll
        for (int j = 0; j < 8; j++) o[j] = expf(acc[i][j] - sq) * INV_SQRT_NF;
        size_t base = ((size_t)bh * TLEN + t0 + t) * NFEAT + fg * 8;
        *(float4*)&dst[base]     = make_float4(o[0], o[1], o[2], o[3]);
        *(float4*)&dst[base + 4] = make_float4(o[4], o[5], o[6], o[7]);
    }
}

// ===========================================================================
// Pass 1: per (bh, chunk) compute KVc[f][e] = sum_t kp[t][f]*v[t][e], zc[f].
// ===========================================================================
__global__ __launch_bounds__(256)
void chunk_kv_kernel()
{
    extern __shared__ float sm[];
    float* kps = sm;            // 64*128 = 8192, [t*128+f]
    float* vs  = sm + 8192;     // 64*64  = 4096, [t*64+e]

    const int bh = blockIdx.x >> 5;
    const int c  = blockIdx.x & 31;
    const int b  = bh >> 4, h = bh & 15;
    const int t0 = c * CHK;
    const int tid = threadIdx.x;

    for (int i = tid; i < 8192; i += 256)
        kps[i] = g_kp[((size_t)bh * TLEN + t0 + (i >> 7)) * NFEAT + (i & 127)];
    for (int i = tid; i < 4096; i += 256)
        vs[i] = g_v[((size_t)b * TLEN + t0 + (i >> 6)) * DM + h * HDIM + (i & 63)];
    __syncthreads();

    const int fg = tid >> 3;    // 0..31 -> 4 f
    const int eg = tid & 7;     // 0..7  -> 8 e
    float acc[4][8];
#pragma unroll
    for (int i = 0; i < 4; i++)
#pragma unroll
        for (int j = 0; j < 8; j++) acc[i][j] = 0.f;

#pragma unroll 4
    for (int t = 0; t < CHK; t++) {
        float kf[4];
        *(float4*)kf = *(const float4*)&kps[t * 128 + fg * 4];
        float vv[8];
        *(float4*)&vv[0] = *(const float4*)&vs[t * 64 + eg * 8];
        *(float4*)&vv[4] = *(const float4*)&vs[t * 64 + eg * 8 + 4];
#pragma unroll
        for (int i = 0; i < 4; i++)
#pragma unroll
            for (int j = 0; j < 8; j++) acc[i][j] += kf[i] * vv[j];
    }

    size_t base = ((size_t)bh * NCH + c) * (NFEAT * HDIM);
#pragma unroll
    for (int i = 0; i < 4; i++) {
        size_t r = base + (size_t)(fg * 4 + i) * HDIM + eg * 8;
        *(float4*)&g_kv[r]     = make_float4(acc[i][0], acc[i][1], acc[i][2], acc[i][3]);
        *(float4*)&g_kv[r + 4] = make_float4(acc[i][4], acc[i][5], acc[i][6], acc[i][7]);
    }

    if (tid < NFEAT) {
        float s = 0.f;
#pragma unroll 8
        for (int t = 0; t < CHK; t++) s += kps[t * 128 + tid];
        g_zc[((size_t)bh * NCH + c) * NFEAT + tid] = s;
    }
}

// ===========================================================================
// Exclusive prefix over chunks (in place).
// ===========================================================================
__global__ void prefix_kv_kernel()
{
    int idx = blockIdx.x * 256 + threadIdx.x;      // 524288 total
    int bh = idx >> 13;
    int fe = idx & 8191;
    float* p = g_kv + (size_t)bh * NCH * 8192 + fe;
    float acc = 0.f;
#pragma unroll
    for (int c = 0; c < NCH; c++) {
        float t = p[(size_t)c * 8192];
        p[(size_t)c * 8192] = acc;
        acc += t;
    }
}

__global__ void prefix_z_kernel()
{
    int idx = blockIdx.x * 256 + threadIdx.x;      // 8192 total
    int bh = idx >> 7;
    int f  = idx & 127;
    float* p = g_zc + (size_t)bh * NCH * NFEAT + f;
    float acc = 0.f;
#pragma unroll
    for (int c = 0; c < NCH; c++) {
        float t = p[c * NFEAT];
        p[c * NFEAT] = acc;
        acc += t;
    }
}

// ===========================================================================
// Pass 2: per (bh, chunk): intra (causal A=qp kp^T) + inter (qp @ S_prefix),
// normalize, write y in [b*T+t][h*64+e] layout.
// ===========================================================================
__global__ __launch_bounds__(256)
void attn_out_kernel()
{
    extern __shared__ float sm[];
    float* Ss   = sm;                       // 8192   [f*64+e]
    float* zs   = Ss + 8192;                // 128
    float* qps  = zs + 128;                 // 64*132 = 8448  [t*132+f] (pad)
    float* kpt  = qps + 8448;               // 128*68 = 8704  [f*68+t]  (pad)
    float* vsm  = kpt + 8704;               // 4096   [t*64+e]
    float* Asm  = vsm + 4096;               // 64*68  = 4352  [t*68+s]  (pad, masked)
    float* dens = Asm + 4352;               // 64

    const int bh = blockIdx.x >> 5;
    const int c  = blockIdx.x & 31;
    const int b  = bh >> 4, h = bh & 15;
    const int t0 = c * CHK;
    const int tid = threadIdx.x;

    {
        size_t base = ((size_t)bh * NCH + c) * 8192;
        for (int i = tid; i < 8192; i += 256) Ss[i] = g_kv[base + i];
        if (tid < 128) zs[tid] = g_zc[((size_t)bh * NCH + c) * NFEAT + tid];
        for (int i = tid; i < 8192; i += 256) {
            int t = i >> 7, f = i & 127;
            qps[t * 132 + f] = g_qp[((size_t)bh * TLEN + t0 + t) * NFEAT + f];
            kpt[f * 68 + t]  = g_kp[((size_t)bh * TLEN + t0 + t) * NFEAT + f];
        }
        for (int i = tid; i < 4096; i += 256)
            vsm[i] = g_v[((size_t)b * TLEN + t0 + (i >> 6)) * DM + h * HDIM + (i & 63)];
    }
    __syncthreads();

    // ---- A[t][s] = sum_f qp[t][f] * kp[s][f], masked to s <= t ----
    {
        const int tg = tid >> 4, sg = tid & 15;
        float acc[4][4];
#pragma unroll
        for (int i = 0; i < 4; i++)
#pragma unroll
            for (int j = 0; j < 4; j++) acc[i][j] = 0.f;
#pragma unroll 4
        for (int f = 0; f < NFEAT; f++) {
            float qv[4];
#pragma unroll
            for (int i = 0; i < 4; i++) qv[i] = qps[(tg * 4 + i) * 132 + f];
            float kv[4];
            *(float4*)kv = *(const float4*)&kpt[f * 68 + sg * 4];
#pragma unroll
            for (int i = 0; i < 4; i++)
#pragma unroll
                for (int j = 0; j < 4; j++) acc[i][j] += qv[i] * kv[j];
        }
#pragma unroll
        for (int i = 0; i < 4; i++)
#pragma unroll
            for (int j = 0; j < 4; j++) {
                int t = tg * 4 + i, s = sg * 4 + j;
                Asm[t * 68 + s] = (s <= t) ? acc[i][j] : 0.f;
            }
    }
    __syncthreads();

    // ---- den[t] = rowsum(A_masked) + qp[t].z_prefix + EPS ----
    if (tid < 64) {
        int t = tid;
        float d = 0.f;
#pragma unroll 8
        for (int s = 0; s < CHK; s++) d += Asm[t * 68 + s];
        float d2 = 0.f;
#pragma unroll 8
        for (int f = 0; f < NFEAT; f++) d2 += qps[t * 132 + f] * zs[f];
        dens[t] = d + d2 + EPS_F;
    }
    __syncthreads();

    // ---- num[t][e] = qp @ S_prefix + A_masked @ v ; y = num/den ----
    {
        const int tg = tid >> 4, eg = tid & 15;
        float acc[4][4];
#pragma unroll
        for (int i = 0; i < 4; i++)
#pragma unroll
            for (int j = 0; j < 4; j++) acc[i][j] = 0.f;

#pragma unroll 4
        for (int f = 0; f < NFEAT; f++) {
            float qv[4];
#pragma unroll
            for (int i = 0; i < 4; i++) qv[i] = qps[(tg * 4 + i) * 132 + f];
            float sv[4];
            *(float4*)sv = *(const float4*)&Ss[f * 64 + eg * 4];
#pragma unroll
            for (int i = 0; i < 4; i++)
#pragma unroll
                for (int j = 0; j < 4; j++) acc[i][j] += qv[i] * sv[j];
        }
#pragma unroll 4
        for (int s = 0; s < CHK; s++) {
            float av[4];
#pragma unroll
            for (int i = 0; i < 4; i++) av[i] = Asm[(tg * 4 + i) * 68 + s];
            float vv[4];
            *(float4*)vv = *(const float4*)&vsm[s * 64 + eg * 4];
#pragma unroll
            for (int i = 0; i < 4; i++)
#pragma unroll
                for (int j = 0; j < 4; j++) acc[i][j] += av[i] * vv[j];
        }

#pragma unroll
        for (int i = 0; i < 4; i++) {
            int t = tg * 4 + i;
            float inv = 1.f / dens[t];
            float4 o = make_float4(acc[i][0] * inv, acc[i][1] * inv,
                                   acc[i][2] * inv, acc[i][3] * inv);
            *(float4*)&g_y[((size_t)b * TLEN + t0 + t) * DM + h * HDIM + eg * 4] = o;
        }
    }
}

// ===========================================================================
// kernel_launch
// ===========================================================================
extern "C" void kernel_launch(void* const* d_in, const int* in_sizes, int n_in,
                              void* d_out, int out_size)
{
    const float* x  = (const float*)d_in[0];
    const float* Wq = (const float*)d_in[1];
    const float* Wk = (const float*)d_in[2];
    const float* Wv = (const float*)d_in[3];
    const float* Wo = (const float*)d_in[4];
    const float* Wf = (const float*)d_in[5];
    float* out = (float*)d_out;

    float *gq, *gk, *gv, *gy;
    cudaGetSymbolAddress((void**)&gq, g_q);
    cudaGetSymbolAddress((void**)&gk, g_k);
    cudaGetSymbolAddress((void**)&gv, g_v);
    cudaGetSymbolAddress((void**)&gy, g_y);
    float *gqp, *gkp;
    cudaGetSymbolAddress((void**)&gqp, g_qp);
    cudaGetSymbolAddress((void**)&gkp, g_kp);

    const int feat_smem = (8192 + 4096 + 64) * 4;                 // 49408 B
    const int p1_smem   = (8192 + 4096) * 4;                      // 49152 B
    const int p2_smem   = (8192 + 128 + 8448 + 8704 + 4096 + 4352 + 64) * 4; // 135936 B
    cudaFuncSetAttribute(feat_kernel,     cudaFuncAttributeMaxDynamicSharedMemorySize, feat_smem);
    cudaFuncSetAttribute(chunk_kv_kernel, cudaFuncAttributeMaxDynamicSharedMemorySize, p1_smem);
    cudaFuncSetAttribute(attn_out_kernel, cudaFuncAttributeMaxDynamicSharedMemorySize, p2_smem);

    dim3 gGemm(DM / 128, NROWS / 128);   // (8, 64)

    // QKV projections
    sgemm128<<<gGemm, 256>>>(x, Wq, gq, NROWS, DM, DM);
    sgemm128<<<gGemm, 256>>>(x, Wk, gk, NROWS, DM, DM);
    sgemm128<<<gGemm, 256>>>(x, Wv, gv, NROWS, DM, DM);

    // FAVOR+ feature maps
    feat_kernel<<<BH * NCH, 256, feat_smem>>>(gq, Wf, gqp);
    feat_kernel<<<BH * NCH, 256, feat_smem>>>(gk, Wf, gkp);

    // Chunked causal linear attention
    chunk_kv_kernel<<<BH * NCH, 256, p1_smem>>>();
    prefix_kv_kernel<<<(BH * NFEAT * HDIM) / 256, 256>>>();
    prefix_z_kernel<<<(BH * NFEAT) / 256, 256>>>();
    attn_out_kernel<<<BH * NCH, 256, p2_smem>>>();

    // Output projection straight into d_out
    sgemm128<<<gGemm, 256>>>(gy, Wo, out, NROWS, DM, DM);
}

// round 5
// speedup vs baseline: 1.1166x; 1.1166x over previous
#include <cuda_runtime.h>
#include <cuda_bf16.h>
#include <math.h>
#include <stdint.h>

// Problem constants
#define TLEN   2048
#define NHEAD  16
#define HDIM   64
#define NFEAT  128
#define BATCH  4
#define BH     64
#define NROWS  8192        // BATCH*TLEN
#define DM     1024
#define NCH    32
#define CHK    64
#define EPS_F  1e-6f
#define INV_SQRT_NF 0.08838834764831843f

// -------------------- scratch (device globals) -----------------------------
__device__ float g_q [NROWS * DM];
__device__ float g_k [NROWS * DM];
__device__ float g_v [NROWS * DM];
__device__ float g_y [NROWS * DM];
__device__ float g_qe[(size_t)NROWS * 2048];   // x @ Wqf  (exponent, pre-norm)
__device__ float g_ke[(size_t)NROWS * 2048];
__device__ float g_qp[(size_t)BH * TLEN * NFEAT];
__device__ float g_kp[(size_t)BH * TLEN * NFEAT];
__device__ float g_kv[(size_t)BH * NCH * NFEAT * HDIM];
__device__ float g_zc[(size_t)BH * NCH * NFEAT];

// bf16 split operands
__device__ __nv_bfloat16 g_xh[(size_t)NROWS * DM];
__device__ __nv_bfloat16 g_xl[(size_t)NROWS * DM];
__device__ __nv_bfloat16 g_yh[(size_t)NROWS * DM];
__device__ __nv_bfloat16 g_yl[(size_t)NROWS * DM];
__device__ __nv_bfloat16 g_Wqt_h[DM * DM], g_Wqt_l[DM * DM];
__device__ __nv_bfloat16 g_Wkt_h[DM * DM], g_Wkt_l[DM * DM];
__device__ __nv_bfloat16 g_Wvt_h[DM * DM], g_Wvt_l[DM * DM];
__device__ __nv_bfloat16 g_Wot_h[DM * DM], g_Wot_l[DM * DM];
__device__ __nv_bfloat16 g_Wqf_h[2048 * DM], g_Wqf_l[2048 * DM];
__device__ __nv_bfloat16 g_Wkf_h[2048 * DM], g_Wkf_l[2048 * DM];

// ===========================================================================
// Low-level helpers (compute_103-safe: cp.async / ldmatrix / mma.sync only)
// ===========================================================================
__device__ __forceinline__ uint32_t smem_u32(const void* p) {
    uint32_t a;
    asm("{ .reg .u64 t; cvta.to.shared.u64 t, %1; cvt.u32.u64 %0, t; }"
        : "=r"(a) : "l"(p));
    return a;
}
__device__ __forceinline__ void cp16(uint32_t dst, const void* src) {
    asm volatile("cp.async.cg.shared.global [%0], [%1], 16;"
                 :: "r"(dst), "l"(src) : "memory");
}
__device__ __forceinline__ void ldsm4(uint32_t* r, uint32_t a) {
    asm volatile("ldmatrix.sync.aligned.m8n8.x4.shared.b16 {%0,%1,%2,%3}, [%4];"
                 : "=r"(r[0]), "=r"(r[1]), "=r"(r[2]), "=r"(r[3]) : "r"(a));
}
__device__ __forceinline__ void ldsm2(uint32_t* r, uint32_t a) {
    asm volatile("ldmatrix.sync.aligned.m8n8.x2.shared.b16 {%0,%1}, [%2];"
                 : "=r"(r[0]), "=r"(r[1]) : "r"(a));
}
__device__ __forceinline__ void mma16816(float* c, const uint32_t* a, const uint32_t* b) {
    asm volatile("mma.sync.aligned.m16n8k16.row.col.f32.bf16.bf16.f32 "
                 "{%0,%1,%2,%3}, {%4,%5,%6,%7}, {%8,%9}, {%0,%1,%2,%3};"
                 : "+f"(c[0]), "+f"(c[1]), "+f"(c[2]), "+f"(c[3])
                 : "r"(a[0]), "r"(a[1]), "r"(a[2]), "r"(a[3]),
                   "r"(b[0]), "r"(b[1]));
}

// ===========================================================================
// Tensor-core split-bf16 GEMM: C[M,N] = A[M,1024] @ Bt[N,1024]^T
//   A ~ Ah+Al, B ~ Bh+Bl (bf16);  D = AhBh + AlBh + AhBl  (fp32 accum)
// 128x128 CTA tile, BK=32, 3-stage cp.async pipeline, 8 warps (64x32 each).
// ===========================================================================
#define BKC     32
#define NSTG    3
#define APITCH  40                      // 32 k + 8 pad (80 B rows, 16B aligned)
#define OPBYTES (128 * APITCH * 2)      // 10240 per operand tile
#define STGB    (4 * OPBYTES)           // 40960 per stage
#define KCNT    (DM / BKC)              // 32 chunks

__global__ __launch_bounds__(256, 1)
void gemm_mma_x3(const __nv_bfloat16* __restrict__ Ah, const __nv_bfloat16* __restrict__ Al,
                 const __nv_bfloat16* __restrict__ Bh, const __nv_bfloat16* __restrict__ Bl,
                 float* __restrict__ C, int N)
{
    extern __shared__ __align__(16) char smem[];
    const int tid  = threadIdx.x;
    const int lane = tid & 31, wid = tid >> 5;
    const int m0 = blockIdx.y * 128;
    const int n0 = blockIdx.x * 128;
    const int wm = (wid >> 2) * 64;     // warp m offset in tile
    const int wn = (wid & 3) * 32;      // warp n offset in tile

    const __nv_bfloat16* pAh = Ah + (size_t)m0 * DM;
    const __nv_bfloat16* pAl = Al + (size_t)m0 * DM;
    const __nv_bfloat16* pBh = Bh + (size_t)n0 * DM;
    const __nv_bfloat16* pBl = Bl + (size_t)n0 * DM;
    const uint32_t sbase = smem_u32(smem);

    float acc[4][4][4];
#pragma unroll
    for (int i = 0; i < 4; i++)
#pragma unroll
        for (int j = 0; j < 4; j++)
#pragma unroll
            for (int r = 0; r < 4; r++) acc[i][j][r] = 0.f;

    // ---- stage loader: 4 operand tiles of 128 x 32 bf16 each -------------
    auto load_stage = [&](int kc, int s) {
        const uint32_t d0 = sbase + s * STGB;
        const int k0 = kc * BKC;
#pragma unroll
        for (int u0 = 0; u0 < 2; u0++) {
            int u = u0 * 256 + tid;             // 0..511
            int r = u >> 2;
            int c = u & 3;
            uint32_t doff = (uint32_t)(r * APITCH + c * 8) * 2;
            size_t   goff = (size_t)r * DM + k0 + c * 8;
            cp16(d0 + 0 * OPBYTES + doff, pAh + goff);
            cp16(d0 + 1 * OPBYTES + doff, pAl + goff);
            cp16(d0 + 2 * OPBYTES + doff, pBh + goff);
            cp16(d0 + 3 * OPBYTES + doff, pBl + goff);
        }
        asm volatile("cp.async.commit_group;" ::: "memory");
    };

    // per-thread ldmatrix base offsets (within an operand tile)
    const int l16 = lane & 15;
    const uint32_t aOff = (uint32_t)((wm + l16) * APITCH + (lane >> 4) * 8) * 2;
    const uint32_t bOff = (uint32_t)((wn + (l16 & 7)) * APITCH + (l16 >> 3) * 8) * 2;

    auto compute_stage = [&](int s) {
        const uint32_t st = sbase + s * STGB;
        const uint32_t aH = st + aOff;
        const uint32_t aL = aH + OPBYTES;
        const uint32_t bH = st + 2 * OPBYTES + bOff;
        const uint32_t bL = bH + OPBYTES;
#pragma unroll
        for (int ks = 0; ks < 2; ks++) {
            uint32_t ah[4][4], al[4][4], bh[4][2], bl[4][2];
#pragma unroll
            for (int i = 0; i < 4; i++) {
                ldsm4(ah[i], aH + i * (16 * APITCH * 2) + ks * 32);
                ldsm4(al[i], aL + i * (16 * APITCH * 2) + ks * 32);
            }
#pragma unroll
            for (int j = 0; j < 4; j++) {
                ldsm2(bh[j], bH + j * (8 * APITCH * 2) + ks * 32);
                ldsm2(bl[j], bL + j * (8 * APITCH * 2) + ks * 32);
            }
#pragma unroll
            for (int i = 0; i < 4; i++)
#pragma unroll
                for (int j = 0; j < 4; j++) {
                    mma16816(acc[i][j], ah[i], bh[j]);
                    mma16816(acc[i][j], al[i], bh[j]);
                    mma16816(acc[i][j], ah[i], bl[j]);
                }
        }
    };

    load_stage(0, 0);
    load_stage(1, 1);

    for (int kc = 0; kc < KCNT; kc++) {
        if (kc + 2 < KCNT)
            asm volatile("cp.async.wait_group 1;" ::: "memory");
        else
            asm volatile("cp.async.wait_group 0;" ::: "memory");
        __syncthreads();
        if (kc + 2 < KCNT) load_stage(kc + 2, (kc + 2) % NSTG);
        compute_stage(kc % NSTG);
    }

    // ---- epilogue -----------------------------------------------------------
    const int g  = lane >> 2;
    const int tg = lane & 3;
#pragma unroll
    for (int i = 0; i < 4; i++) {
        const int row = m0 + wm + i * 16 + g;
#pragma unroll
        for (int j = 0; j < 4; j++) {
            const int col = n0 + wn + j * 8 + tg * 2;
            *(float2*)&C[(size_t)row * N + col]       = make_float2(acc[i][j][0], acc[i][j][1]);
            *(float2*)&C[(size_t)(row + 8) * N + col] = make_float2(acc[i][j][2], acc[i][j][3]);
        }
    }
}

// ===========================================================================
// Split fp32 -> bf16 hi/lo (same layout)
// ===========================================================================
__global__ __launch_bounds__(256)
void split_fp32(const float* __restrict__ src, __nv_bfloat16* __restrict__ h,
                __nv_bfloat16* __restrict__ l, int n4)
{
    int i = blockIdx.x * 256 + threadIdx.x;
    if (i >= n4) return;
    float4 v = ((const float4*)src)[i];
    __nv_bfloat16 h0 = __float2bfloat16(v.x), h1 = __float2bfloat16(v.y);
    __nv_bfloat16 h2 = __float2bfloat16(v.z), h3 = __float2bfloat16(v.w);
    __nv_bfloat16 l0 = __float2bfloat16(v.x - __bfloat162float(h0));
    __nv_bfloat16 l1 = __float2bfloat16(v.y - __bfloat162float(h1));
    __nv_bfloat16 l2 = __float2bfloat16(v.z - __bfloat162float(h2));
    __nv_bfloat16 l3 = __float2bfloat16(v.w - __bfloat162float(h3));
    ((__nv_bfloat162*)h)[2 * i]     = __halves2bfloat162(h0, h1);
    ((__nv_bfloat162*)h)[2 * i + 1] = __halves2bfloat162(h2, h3);
    ((__nv_bfloat162*)l)[2 * i]     = __halves2bfloat162(l0, l1);
    ((__nv_bfloat162*)l)[2 * i + 1] = __halves2bfloat162(l2, l3);
}

// ===========================================================================
// Transpose + split: W[1024,1024] fp32 -> Wt hi/lo [n][k] bf16
// ===========================================================================
__global__ void trans_split(const float* __restrict__ W,
                            __nv_bfloat16* __restrict__ th, __nv_bfloat16* __restrict__ tl)
{
    __shared__ float tile[32][33];
    const int bx = blockIdx.x, by = blockIdx.y;
    const int tx = threadIdx.x, ty = threadIdx.y;   // 32 x 8
#pragma unroll
    for (int j = 0; j < 32; j += 8)
        tile[ty + j][tx] = W[(size_t)(by * 32 + ty + j) * DM + bx * 32 + tx];
    __syncthreads();
#pragma unroll
    for (int j = 0; j < 32; j += 8) {
        float v = tile[tx][ty + j];                 // = W[by*32+tx][bx*32+ty+j]
        __nv_bfloat16 h = __float2bfloat16(v);
        __nv_bfloat16 l = __float2bfloat16(v - __bfloat162float(h));
        size_t o = (size_t)(bx * 32 + ty + j) * DM + by * 32 + tx;
        th[o] = h;
        tl[o] = l;
    }
}

// ===========================================================================
// Wf fold: out[n=h*128+f][k] = sum_d W[k][h*64+d] * Wf[d][f]   (split bf16)
// ===========================================================================
__global__ __launch_bounds__(256)
void wf_fold_kernel(const float* __restrict__ W, const float* __restrict__ Wf,
                    __nv_bfloat16* __restrict__ oh, __nv_bfloat16* __restrict__ ol)
{
    extern __shared__ float fsm[];
    float* Ws = fsm;           // [128 k][64 d]
    float* Fs = fsm + 8192;    // [64 d][128 f]
    const int kb = blockIdx.x, h = blockIdx.y;
    const int tid = threadIdx.x;

    for (int i = tid; i < 8192; i += 256)
        Ws[i] = W[(size_t)(kb * 128 + (i >> 6)) * DM + h * 64 + (i & 63)];
    for (int i = tid; i < 8192; i += 256)
        Fs[i] = Wf[i];
    __syncthreads();

    const int f  = tid & 127;
    const int kh = tid >> 7;
    for (int kk = 0; kk < 64; kk++) {
        int k = kh * 64 + kk;
        float acc = 0.f;
#pragma unroll 16
        for (int d = 0; d < 64; d++) acc += Ws[k * 64 + d] * Fs[d * 128 + f];
        __nv_bfloat16 hi = __float2bfloat16(acc);
        __nv_bfloat16 lo = __float2bfloat16(acc - __bfloat162float(hi));
        size_t o = (size_t)(h * 128 + f) * DM + kb * 128 + k;
        oh[o] = hi;
        ol[o] = lo;
    }
}

// ===========================================================================
// phi = exp(e - 0.5|q_head|^2) / sqrt(NF); one warp per (b,t,h)
// ===========================================================================
__global__ __launch_bounds__(256)
void feat_exp(const float* __restrict__ q, const float* __restrict__ e,
              float* __restrict__ out)
{
    const int gw   = blockIdx.x * 8 + (threadIdx.x >> 5);
    const int lane = threadIdx.x & 31;
    const int bt = gw >> 4;
    const int h  = gw & 15;
    float2 q2 = *(const float2*)&q[(size_t)bt * DM + h * 64 + lane * 2];
    float s = q2.x * q2.x + q2.y * q2.y;
#pragma unroll
    for (int o = 16; o > 0; o >>= 1) s += __shfl_xor_sync(0xffffffffu, s, o);
    const float sq = 0.5f * s;
    float4 ev = *(const float4*)&e[(size_t)bt * 2048 + h * 128 + lane * 4];
    const int b = bt >> 11, t = bt & 2047;
    const int bh = b * 16 + h;
    float4 o4 = make_float4(expf(ev.x - sq) * INV_SQRT_NF, expf(ev.y - sq) * INV_SQRT_NF,
                            expf(ev.z - sq) * INV_SQRT_NF, expf(ev.w - sq) * INV_SQRT_NF);
    *(float4*)&out[((size_t)bh * TLEN + t) * NFEAT + lane * 4] = o4;
}

// ===========================================================================
// Attention mid-section (validated in R2)
// ===========================================================================
__global__ __launch_bounds__(256)
void chunk_kv_kernel()
{
    extern __shared__ float sm[];
    float* kps = sm;
    float* vs  = sm + 8192;

    const int bh = blockIdx.x >> 5;
    const int c  = blockIdx.x & 31;
    const int b  = bh >> 4, h = bh & 15;
    const int t0 = c * CHK;
    const int tid = threadIdx.x;

    for (int i = tid; i < 8192; i += 256)
        kps[i] = g_kp[((size_t)bh * TLEN + t0 + (i >> 7)) * NFEAT + (i & 127)];
    for (int i = tid; i < 4096; i += 256)
        vs[i] = g_v[((size_t)b * TLEN + t0 + (i >> 6)) * DM + h * HDIM + (i & 63)];
    __syncthreads();

    const int fg = tid >> 3;
    const int eg = tid & 7;
    float acc[4][8];
#pragma unroll
    for (int i = 0; i < 4; i++)
#pragma unroll
        for (int j = 0; j < 8; j++) acc[i][j] = 0.f;

#pragma unroll 4
    for (int t = 0; t < CHK; t++) {
        float kf[4];
        *(float4*)kf = *(const float4*)&kps[t * 128 + fg * 4];
        float vv[8];
        *(float4*)&vv[0] = *(const float4*)&vs[t * 64 + eg * 8];
        *(float4*)&vv[4] = *(const float4*)&vs[t * 64 + eg * 8 + 4];
#pragma unroll
        for (int i = 0; i < 4; i++)
#pragma unroll
            for (int j = 0; j < 8; j++) acc[i][j] += kf[i] * vv[j];
    }

    size_t base = ((size_t)bh * NCH + c) * (NFEAT * HDIM);
#pragma unroll
    for (int i = 0; i < 4; i++) {
        size_t r = base + (size_t)(fg * 4 + i) * HDIM + eg * 8;
        *(float4*)&g_kv[r]     = make_float4(acc[i][0], acc[i][1], acc[i][2], acc[i][3]);
        *(float4*)&g_kv[r + 4] = make_float4(acc[i][4], acc[i][5], acc[i][6], acc[i][7]);
    }

    if (tid < NFEAT) {
        float s = 0.f;
#pragma unroll 8
        for (int t = 0; t < CHK; t++) s += kps[t * 128 + tid];
        g_zc[((size_t)bh * NCH + c) * NFEAT + tid] = s;
    }
}

__global__ void prefix_kv_kernel()
{
    int idx = blockIdx.x * 256 + threadIdx.x;
    int bh = idx >> 13;
    int fe = idx & 8191;
    float* p = g_kv + (size_t)bh * NCH * 8192 + fe;
    float acc = 0.f;
#pragma unroll
    for (int c = 0; c < NCH; c++) {
        float t = p[(size_t)c * 8192];
        p[(size_t)c * 8192] = acc;
        acc += t;
    }
}

__global__ void prefix_z_kernel()
{
    int idx = blockIdx.x * 256 + threadIdx.x;
    int bh = idx >> 7;
    int f  = idx & 127;
    float* p = g_zc + (size_t)bh * NCH * NFEAT + f;
    float acc = 0.f;
#pragma unroll
    for (int c = 0; c < NCH; c++) {
        float t = p[c * NFEAT];
        p[c * NFEAT] = acc;
        acc += t;
    }
}

__global__ __launch_bounds__(256)
void attn_out_kernel()
{
    extern __shared__ float sm[];
    float* Ss   = sm;
    float* zs   = Ss + 8192;
    float* qps  = zs + 128;
    float* kpt  = qps + 8448;
    float* vsm  = kpt + 8704;
    float* Asm  = vsm + 4096;
    float* dens = Asm + 4352;

    const int bh = blockIdx.x >> 5;
    const int c  = blockIdx.x & 31;
    const int b  = bh >> 4, h = bh & 15;
    const int t0 = c * CHK;
    const int tid = threadIdx.x;

    {
        size_t base = ((size_t)bh * NCH + c) * 8192;
        for (int i = tid; i < 8192; i += 256) Ss[i] = g_kv[base + i];
        if (tid < 128) zs[tid] = g_zc[((size_t)bh * NCH + c) * NFEAT + tid];
        for (int i = tid; i < 8192; i += 256) {
            int t = i >> 7, f = i & 127;
            qps[t * 132 + f] = g_qp[((size_t)bh * TLEN + t0 + t) * NFEAT + f];
            kpt[f * 68 + t]  = g_kp[((size_t)bh * TLEN + t0 + t) * NFEAT + f];
        }
        for (int i = tid; i < 4096; i += 256)
            vsm[i] = g_v[((size_t)b * TLEN + t0 + (i >> 6)) * DM + h * HDIM + (i & 63)];
    }
    __syncthreads();

    {
        const int tg = tid >> 4, sg = tid & 15;
        float acc[4][4];
#pragma unroll
        for (int i = 0; i < 4; i++)
#pragma unroll
            for (int j = 0; j < 4; j++) acc[i][j] = 0.f;
#pragma unroll 4
        for (int f = 0; f < NFEAT; f++) {
            float qv[4];
#pragma unroll
            for (int i = 0; i < 4; i++) qv[i] = qps[(tg * 4 + i) * 132 + f];
            float kv[4];
            *(float4*)kv = *(const float4*)&kpt[f * 68 + sg * 4];
#pragma unroll
            for (int i = 0; i < 4; i++)
#pragma unroll
                for (int j = 0; j < 4; j++) acc[i][j] += qv[i] * kv[j];
        }
#pragma unroll
        for (int i = 0; i < 4; i++)
#pragma unroll
            for (int j = 0; j < 4; j++) {
                int t = tg * 4 + i, s = sg * 4 + j;
                Asm[t * 68 + s] = (s <= t) ? acc[i][j] : 0.f;
            }
    }
    __syncthreads();

    if (tid < 64) {
        int t = tid;
        float d = 0.f;
#pragma unroll 8
        for (int s = 0; s < CHK; s++) d += Asm[t * 68 + s];
        float d2 = 0.f;
#pragma unroll 8
        for (int f = 0; f < NFEAT; f++) d2 += qps[t * 132 + f] * zs[f];
        dens[t] = d + d2 + EPS_F;
    }
    __syncthreads();

    {
        const int tg = tid >> 4, eg = tid & 15;
        float acc[4][4];
#pragma unroll
        for (int i = 0; i < 4; i++)
#pragma unroll
            for (int j = 0; j < 4; j++) acc[i][j] = 0.f;

#pragma unroll 4
        for (int f = 0; f < NFEAT; f++) {
            float qv[4];
#pragma unroll
            for (int i = 0; i < 4; i++) qv[i] = qps[(tg * 4 + i) * 132 + f];
            float sv[4];
            *(float4*)sv = *(const float4*)&Ss[f * 64 + eg * 4];
#pragma unroll
            for (int i = 0; i < 4; i++)
#pragma unroll
                for (int j = 0; j < 4; j++) acc[i][j] += qv[i] * sv[j];
        }
#pragma unroll 4
        for (int s = 0; s < CHK; s++) {
            float av[4];
#pragma unroll
            for (int i = 0; i < 4; i++) av[i] = Asm[(tg * 4 + i) * 68 + s];
            float vv[4];
            *(float4*)vv = *(const float4*)&vsm[s * 64 + eg * 4];
#pragma unroll
            for (int i = 0; i < 4; i++)
#pragma unroll
                for (int j = 0; j < 4; j++) acc[i][j] += av[i] * vv[j];
        }

#pragma unroll
        for (int i = 0; i < 4; i++) {
            int t = tg * 4 + i;
            float inv = 1.f / dens[t];
            float4 o = make_float4(acc[i][0] * inv, acc[i][1] * inv,
                                   acc[i][2] * inv, acc[i][3] * inv);
            *(float4*)&g_y[((size_t)b * TLEN + t0 + t) * DM + h * HDIM + eg * 4] = o;
        }
    }
}

// ===========================================================================
// kernel_launch
// ===========================================================================
extern "C" void kernel_launch(void* const* d_in, const int* in_sizes, int n_in,
                              void* d_out, int out_size)
{
    const float* x  = (const float*)d_in[0];
    const float* Wq = (const float*)d_in[1];
    const float* Wk = (const float*)d_in[2];
    const float* Wv = (const float*)d_in[3];
    const float* Wo = (const float*)d_in[4];
    const float* Wf = (const float*)d_in[5];
    float* out = (float*)d_out;

    float *gq, *gk, *gv, *gy, *gqe, *gke, *gqp, *gkp;
    cudaGetSymbolAddress((void**)&gq,  g_q);
    cudaGetSymbolAddress((void**)&gk,  g_k);
    cudaGetSymbolAddress((void**)&gv,  g_v);
    cudaGetSymbolAddress((void**)&gy,  g_y);
    cudaGetSymbolAddress((void**)&gqe, g_qe);
    cudaGetSymbolAddress((void**)&gke, g_ke);
    cudaGetSymbolAddress((void**)&gqp, g_qp);
    cudaGetSymbolAddress((void**)&gkp, g_kp);

    __nv_bfloat16 *xh, *xl, *yh, *yl;
    cudaGetSymbolAddress((void**)&xh, g_xh);
    cudaGetSymbolAddress((void**)&xl, g_xl);
    cudaGetSymbolAddress((void**)&yh, g_yh);
    cudaGetSymbolAddress((void**)&yl, g_yl);
    __nv_bfloat16 *wqh, *wql, *wkh, *wkl, *wvh, *wvl, *woh, *wol, *wqfh, *wqfl, *wkfh, *wkfl;
    cudaGetSymbolAddress((void**)&wqh, g_Wqt_h);  cudaGetSymbolAddress((void**)&wql, g_Wqt_l);
    cudaGetSymbolAddress((void**)&wkh, g_Wkt_h);  cudaGetSymbolAddress((void**)&wkl, g_Wkt_l);
    cudaGetSymbolAddress((void**)&wvh, g_Wvt_h);  cudaGetSymbolAddress((void**)&wvl, g_Wvt_l);
    cudaGetSymbolAddress((void**)&woh, g_Wot_h);  cudaGetSymbolAddress((void**)&wol, g_Wot_l);
    cudaGetSymbolAddress((void**)&wqfh, g_Wqf_h); cudaGetSymbolAddress((void**)&wqfl, g_Wqf_l);
    cudaGetSymbolAddress((void**)&wkfh, g_Wkf_h); cudaGetSymbolAddress((void**)&wkfl, g_Wkf_l);

    const int gemm_smem = NSTG * STGB;                            // 122880
    const int fold_smem = 65536;
    const int p1_smem   = (8192 + 4096) * 4;
    const int p2_smem   = (8192 + 128 + 8448 + 8704 + 4096 + 4352 + 64) * 4;
    cudaFuncSetAttribute(gemm_mma_x3,    cudaFuncAttributeMaxDynamicSharedMemorySize, gemm_smem);
    cudaFuncSetAttribute(wf_fold_kernel, cudaFuncAttributeMaxDynamicSharedMemorySize, fold_smem);
    cudaFuncSetAttribute(chunk_kv_kernel, cudaFuncAttributeMaxDynamicSharedMemorySize, p1_smem);
    cudaFuncSetAttribute(attn_out_kernel, cudaFuncAttributeMaxDynamicSharedMemorySize, p2_smem);

    const int n4 = NROWS * DM / 4;

    // Operand preparation
    split_fp32<<<n4 / 256, 256>>>(x, xh, xl, n4);
    dim3 tb(32, 8), tg(32, 32);
    trans_split<<<tg, tb>>>(Wq, wqh, wql);
    trans_split<<<tg, tb>>>(Wk, wkh, wkl);
    trans_split<<<tg, tb>>>(Wv, wvh, wvl);
    trans_split<<<tg, tb>>>(Wo, woh, wol);
    wf_fold_kernel<<<dim3(8, 16), 256, fold_smem>>>(Wq, Wf, wqfh, wqfl);
    wf_fold_kernel<<<dim3(8, 16), 256, fold_smem>>>(Wk, Wf, wkfh, wkfl);

    // Tensor-core GEMMs: projections + fused feature exponents
    dim3 g1(DM / 128, NROWS / 128);       // (8, 64)
    dim3 g2(2048 / 128, NROWS / 128);     // (16, 64)
    gemm_mma_x3<<<g1, 256, gemm_smem>>>(xh, xl, wqh, wql, gq, DM);
    gemm_mma_x3<<<g1, 256, gemm_smem>>>(xh, xl, wkh, wkl, gk, DM);
    gemm_mma_x3<<<g1, 256, gemm_smem>>>(xh, xl, wvh, wvl, gv, DM);
    gemm_mma_x3<<<g2, 256, gemm_smem>>>(xh, xl, wqfh, wqfl, gqe, 2048);
    gemm_mma_x3<<<g2, 256, gemm_smem>>>(xh, xl, wkfh, wkfl, gke, 2048);

    // FAVOR+ feature maps (elementwise)
    feat_exp<<<NROWS * NHEAD / 8, 256>>>(gq, gqe, gqp);
    feat_exp<<<NROWS * NHEAD / 8, 256>>>(gk, gke, gkp);

    // Chunked causal linear attention
    chunk_kv_kernel<<<BH * NCH, 256, p1_smem>>>();
    prefix_kv_kernel<<<(BH * NFEAT * HDIM) / 256, 256>>>();
    prefix_z_kernel<<<(BH * NFEAT) / 256, 256>>>();
    attn_out_kernel<<<BH * NCH, 256, p2_smem>>>();

    // Output projection (tensor cores) straight into d_out
    split_fp32<<<n4 / 256, 256>>>(gy, yh, yl, n4);
    gemm_mma_x3<<<g1, 256, gemm_smem>>>(yh, yl, woh, wol, out, DM);
}